// round 2
// baseline (speedup 1.0000x reference)
#include <cuda_runtime.h>
#include <math.h>

#define T_SEQ 512
#define NB    64
#define NI    256
#define NH    512

// Scratch: input projection result (64 MB) + barrier counter.
__device__ float    g_pre[(size_t)T_SEQ * NB * NH];
__device__ unsigned g_bar;

__global__ void reset_bar() { g_bar = 0u; }

// ---------------------------------------------------------------------------
// GEMM: g_pre[m][j] = sum_k x[m][k] * W_ih[j][k] + b_ih[j] + b_hh[j]
// M = T*B = 32768, N = 512, K = 256.  BM=128, BN=64, BK=16, 256 thr, 8x4 micro.
// ---------------------------------------------------------------------------
#define BM 128
#define BN 64
#define BK 16

__global__ __launch_bounds__(256) void gemm_xw(
    const float* __restrict__ A,    // [M][256]
    const float* __restrict__ Wih,  // [512][256]
    const float* __restrict__ bih,
    const float* __restrict__ bhh)
{
    __shared__ float As[BK][BM + 4];
    __shared__ float Bs[BK][BN + 4];
    const int m0 = blockIdx.y * BM;
    const int n0 = blockIdx.x * BN;
    const int tid = threadIdx.x;
    const int ty = tid >> 4;   // 0..15 -> 8 rows each
    const int tx = tid & 15;   // 0..15 -> 4 cols each

    float acc[8][4];
#pragma unroll
    for (int i = 0; i < 8; ++i)
#pragma unroll
        for (int j = 0; j < 4; ++j) acc[i][j] = 0.f;

    for (int k0 = 0; k0 < NI; k0 += BK) {
        // A tile (128x16) -> As[k][m]
#pragma unroll
        for (int i = 0; i < 2; ++i) {
            int f  = tid + i * 256;       // 0..511 float4s
            int r  = f >> 2;              // row 0..127
            int c4 = f & 3;               // float4 within 16-wide k slab
            float4 v = *(const float4*)(A + (size_t)(m0 + r) * NI + k0 + c4 * 4);
            As[c4 * 4 + 0][r] = v.x;
            As[c4 * 4 + 1][r] = v.y;
            As[c4 * 4 + 2][r] = v.z;
            As[c4 * 4 + 3][r] = v.w;
        }
        // B tile (64x16) -> Bs[k][n]
        {
            int r  = tid >> 2;
            int c4 = tid & 3;
            float4 v = *(const float4*)(Wih + (size_t)(n0 + r) * NI + k0 + c4 * 4);
            Bs[c4 * 4 + 0][r] = v.x;
            Bs[c4 * 4 + 1][r] = v.y;
            Bs[c4 * 4 + 2][r] = v.z;
            Bs[c4 * 4 + 3][r] = v.w;
        }
        __syncthreads();
#pragma unroll
        for (int k = 0; k < BK; ++k) {
            float a[8], b[4];
            *(float4*)&a[0] = *(const float4*)&As[k][ty * 8];
            *(float4*)&a[4] = *(const float4*)&As[k][ty * 8 + 4];
            *(float4*)&b[0] = *(const float4*)&Bs[k][tx * 4];
#pragma unroll
            for (int i = 0; i < 8; ++i)
#pragma unroll
                for (int j = 0; j < 4; ++j)
                    acc[i][j] = fmaf(a[i], b[j], acc[i][j]);
        }
        __syncthreads();
    }

    const int n = n0 + tx * 4;
    float4 bias = make_float4(bih[n + 0] + bhh[n + 0], bih[n + 1] + bhh[n + 1],
                              bih[n + 2] + bhh[n + 2], bih[n + 3] + bhh[n + 3]);
#pragma unroll
    for (int i = 0; i < 8; ++i) {
        float4 o;
        o.x = acc[i][0] + bias.x;
        o.y = acc[i][1] + bias.y;
        o.z = acc[i][2] + bias.z;
        o.w = acc[i][3] + bias.w;
        *(float4*)(g_pre + (size_t)(m0 + ty * 8 + i) * NH + n) = o;
    }
}

// ---------------------------------------------------------------------------
// Persistent recurrence kernel: 128 CTAs (16 j-tiles x 8 b-tiles), 256 thr.
// Thread (warp=b_local, lane=j_local) computes h_t[b][j], K=512 dot.
// W_hh slice cached in smem once; h tile re-read per step via L2 (__ldcg).
// Grid barrier: monotonic atomic counter (reset kernel zeroes it per launch).
// ---------------------------------------------------------------------------
#define RG   128
#define RT   256
#define WPAD 516   // row stride (floats): 516/4=129 odd -> conflict-free LDS.128

__global__ __launch_bounds__(RT) void rnn_recur(
    const float* __restrict__ h0,    // [B][H]
    const float* __restrict__ Whh,   // [H][H]
    float* __restrict__ hseq,        // [T][B][H]
    float* __restrict__ hlast)       // [B][H] or nullptr
{
    extern __shared__ float sm[];
    float* Ws = sm;                // [32][WPAD]
    float* hs = sm + 32 * WPAD;    // [8][WPAD]

    const int jt = blockIdx.x & 15;
    const int bt = blockIdx.x >> 4;
    const int j0 = jt * 32;
    const int b0 = bt * 8;
    const int lane = threadIdx.x & 31;
    const int warp = threadIdx.x >> 5;
    const int j = j0 + lane;
    const int b = b0 + warp;

    // Load this CTA's 32 rows of W_hh into smem once (reused for all 512 steps).
    for (int idx = threadIdx.x; idx < 32 * NH / 4; idx += RT) {
        int r  = idx >> 7;      // /128 float4s per row
        int c4 = idx & 127;
        float4 v = *(const float4*)(Whh + (size_t)(j0 + r) * NH + c4 * 4);
        *(float4*)(Ws + r * WPAD + c4 * 4) = v;
    }

    const float* hprev = h0;
    const float4* wr = (const float4*)(Ws + lane * WPAD);
    const float4* hr = (const float4*)(hs + warp * WPAD);

    for (int t = 0; t < T_SEQ; ++t) {
        // Load h_{t-1} tile (8 batches x 512) from L2.
        for (int idx = threadIdx.x; idx < 8 * NH / 4; idx += RT) {
            int r  = idx >> 7;
            int c4 = idx & 127;
            float4 v = __ldcg((const float4*)(hprev + (size_t)(b0 + r) * NH + c4 * 4));
            *(float4*)(hs + r * WPAD + c4 * 4) = v;
        }
        __syncthreads();

        float a0 = 0.f, a1 = 0.f, a2 = 0.f, a3 = 0.f;
#pragma unroll 8
        for (int k = 0; k < NH / 4; ++k) {
            float4 w = wr[k];
            float4 h = hr[k];
            a0 = fmaf(w.x, h.x, a0);
            a1 = fmaf(w.y, h.y, a1);
            a2 = fmaf(w.z, h.z, a2);
            a3 = fmaf(w.w, h.w, a3);
        }
        float acc = (a0 + a1) + (a2 + a3);

        float pre = g_pre[((size_t)t * NB + b) * NH + j];
        float hv  = tanhf(acc + pre);
        hseq[((size_t)t * NB + b) * NH + j] = hv;
        if (t == T_SEQ - 1 && hlast) hlast[(size_t)b * NH + j] = hv;

        // Release: my store is GPU-visible before my arrival is counted.
        __threadfence();
        __syncthreads();
        if (threadIdx.x == 0) {
            atomicAdd(&g_bar, 1u);
            const unsigned target = (unsigned)(t + 1) * RG;
            while (*(volatile unsigned*)&g_bar < target) { }
            __threadfence();   // acquire
        }
        __syncthreads();

        hprev = hseq + (size_t)t * NB * NH;
    }
}

// ---------------------------------------------------------------------------
extern "C" void kernel_launch(void* const* d_in, const int* in_sizes, int n_in,
                              void* d_out, int out_size)
{
    const float* x    = (const float*)d_in[0];
    const float* h0   = (const float*)d_in[1];
    const float* Wih  = (const float*)d_in[2];
    const float* Whh  = (const float*)d_in[3];
    const float* bih  = (const float*)d_in[4];
    const float* bhh  = (const float*)d_in[5];
    float* out = (float*)d_out;

    float* hlast = nullptr;
    if (out_size >= (int)((size_t)T_SEQ * NB * NH + NB * NH))
        hlast = out + (size_t)T_SEQ * NB * NH;

    reset_bar<<<1, 1>>>();

    dim3 grid(NH / BN, (T_SEQ * NB) / BM);   // (8, 256)
    gemm_xw<<<grid, 256>>>(x, Wih, bih, bhh);

    const size_t smem = (size_t)(32 + 8) * WPAD * sizeof(float);  // 82560 B
    cudaFuncSetAttribute(rnn_recur, cudaFuncAttributeMaxDynamicSharedMemorySize,
                         (int)smem);
    rnn_recur<<<RG, RT, smem>>>(h0, Whh, out, hlast);
}

// round 4
// speedup vs baseline: 1.7659x; 1.7659x over previous
#include <cuda_runtime.h>
#include <math.h>

#define T_SEQ 512
#define NB    64
#define NI    256
#define NH    512

// Scratch: input projection result (64 MB) + barrier counter.
__device__ float    g_pre[(size_t)T_SEQ * NB * NH];
__device__ unsigned g_bar;

__global__ void reset_bar() { g_bar = 0u; }

typedef unsigned long long ull;

// Packed 2x fp32 FMA (sm_10x f32x2 pipe): d = a*b + c elementwise on pairs.
#define FFMA2(d, a, b, c) \
    asm("fma.rn.f32x2 %0, %1, %2, %3;" : "=l"(d) : "l"(a), "l"(b), "l"(c))

__device__ __forceinline__ ull pack2(float lo, float hi) {
    ull r;
    asm("mov.b64 %0, {%1, %2};"
        : "=l"(r) : "r"(__float_as_uint(lo)), "r"(__float_as_uint(hi)));
    return r;
}
__device__ __forceinline__ float2 unpack2(ull v) {
    unsigned lo, hi;
    asm("mov.b64 {%0, %1}, %2;" : "=r"(lo), "=r"(hi) : "l"(v));
    return make_float2(__uint_as_float(lo), __uint_as_float(hi));
}

// ---------------------------------------------------------------------------
// GEMM: g_pre[m][j] = sum_k x[m][k] * W_ih[j][k] + b_ih[j] + b_hh[j]
// M = T*B = 32768, N = 512, K = 256.  BM=128, BN=64, BK=16, 256 thr, 8x4 micro.
// Inner product uses packed f32x2 FMAs (2 fp32 FMA / instr).
// ---------------------------------------------------------------------------
#define BM 128
#define BN 64
#define BK 16

__global__ __launch_bounds__(256) void gemm_xw(
    const float* __restrict__ A,    // [M][256]
    const float* __restrict__ Wih,  // [512][256]
    const float* __restrict__ bih,
    const float* __restrict__ bhh)
{
    __shared__ float As[BK][BM + 4];
    __shared__ float Bs[BK][BN + 4];
    const int m0 = blockIdx.y * BM;
    const int n0 = blockIdx.x * BN;
    const int tid = threadIdx.x;
    const int ty = tid >> 4;   // 0..15 -> 8 rows each
    const int tx = tid & 15;   // 0..15 -> 4 cols each

    ull acc2[8][2];
#pragma unroll
    for (int i = 0; i < 8; ++i) { acc2[i][0] = 0ull; acc2[i][1] = 0ull; }

    for (int k0 = 0; k0 < NI; k0 += BK) {
        // A tile (128x16) -> As[k][m]
#pragma unroll
        for (int i = 0; i < 2; ++i) {
            int f  = tid + i * 256;       // 0..511 float4s
            int r  = f >> 2;              // row 0..127
            int c4 = f & 3;               // float4 within 16-wide k slab
            float4 v = *(const float4*)(A + (size_t)(m0 + r) * NI + k0 + c4 * 4);
            As[c4 * 4 + 0][r] = v.x;
            As[c4 * 4 + 1][r] = v.y;
            As[c4 * 4 + 2][r] = v.z;
            As[c4 * 4 + 3][r] = v.w;
        }
        // B tile (64x16) -> Bs[k][n]
        {
            int r  = tid >> 2;
            int c4 = tid & 3;
            float4 v = *(const float4*)(Wih + (size_t)(n0 + r) * NI + k0 + c4 * 4);
            Bs[c4 * 4 + 0][r] = v.x;
            Bs[c4 * 4 + 1][r] = v.y;
            Bs[c4 * 4 + 2][r] = v.z;
            Bs[c4 * 4 + 3][r] = v.w;
        }
        __syncthreads();
#pragma unroll
        for (int k = 0; k < BK; ++k) {
            float a[8];
            *(float4*)&a[0] = *(const float4*)&As[k][ty * 8];
            *(float4*)&a[4] = *(const float4*)&As[k][ty * 8 + 4];
            ulonglong2 b2 = *(const ulonglong2*)&Bs[k][tx * 4];
#pragma unroll
            for (int i = 0; i < 8; ++i) {
                ull aa = pack2(a[i], a[i]);
                FFMA2(acc2[i][0], aa, b2.x, acc2[i][0]);
                FFMA2(acc2[i][1], aa, b2.y, acc2[i][1]);
            }
        }
        __syncthreads();
    }

    const int n = n0 + tx * 4;
    float4 bias = make_float4(bih[n + 0] + bhh[n + 0], bih[n + 1] + bhh[n + 1],
                              bih[n + 2] + bhh[n + 2], bih[n + 3] + bhh[n + 3]);
#pragma unroll
    for (int i = 0; i < 8; ++i) {
        float2 p0 = unpack2(acc2[i][0]);
        float2 p1 = unpack2(acc2[i][1]);
        float4 o;
        o.x = p0.x + bias.x;
        o.y = p0.y + bias.y;
        o.z = p1.x + bias.z;
        o.w = p1.y + bias.w;
        *(float4*)(g_pre + (size_t)(m0 + ty * 8 + i) * NH + n) = o;
    }
}

// ---------------------------------------------------------------------------
// Persistent recurrence kernel: 128 CTAs (16 j-tiles x 8 b-tiles), 256 thr.
// Thread (lane=j within tile, warp=k-slice of 64) holds W_hh[j][kslice] in
// 64 registers (loaded once). Per step: stage the 8x512 h tile to smem,
// every warp reads its k-slice with broadcast LDS, accumulates 8 partial dots
// (one per batch) with packed f32x2 FMAs, cross-warp reduce via smem, tanh,
// store, grid barrier (monotonic atomic counter).
// ---------------------------------------------------------------------------
#define RG 128
#define RT 256

__global__ __launch_bounds__(RT, 1) void rnn_recur(
    const float* __restrict__ h0,    // [B][H]
    const float* __restrict__ Whh,   // [H][H]
    float* __restrict__ hseq,        // [T][B][H]
    float* __restrict__ hlast)       // [B][H] or nullptr
{
    __shared__ float hs[8 * NH];          // staged h_{t-1} tile (16 KB)
    __shared__ float part[8 * 8 * 32];    // partials [warp][b][lane] (8 KB)

    const int jt   = blockIdx.x & 15;
    const int bt   = blockIdx.x >> 4;
    const int j0   = jt * 32;
    const int b0   = bt * 8;
    const int lane = threadIdx.x & 31;
    const int warp = threadIdx.x >> 5;
    const int j    = j0 + lane;           // output column this thread owns
    const int k0   = warp * 64;           // k-slice this warp owns

    // W_hh[j][k0 .. k0+63] -> 32 packed-pair registers (lives whole kernel).
    ull w2[32];
    {
        const ulonglong2* wp = (const ulonglong2*)(Whh + (size_t)j * NH + k0);
#pragma unroll
        for (int c = 0; c < 16; ++c) {
            ulonglong2 v = __ldg(wp + c);
            w2[2 * c]     = v.x;
            w2[2 * c + 1] = v.y;
        }
    }

    const float* hprev = h0;

    for (int t = 0; t < T_SEQ; ++t) {
        // Prefetch this thread's pre-activation (independent of h).
        float pre = __ldcg(g_pre + ((size_t)t * NB + (b0 + warp)) * NH + j);

        // Stage h_{t-1} tile (8 x 512 floats) L2 -> smem.
#pragma unroll
        for (int r = 0; r < 4; ++r) {
            int idx = threadIdx.x + r * RT;   // 0..1023 float4 slots
            int row = idx >> 7;
            int c4  = idx & 127;
            *(float4*)(hs + row * NH + c4 * 4) =
                __ldcg((const float4*)(hprev + (size_t)(b0 + row) * NH + c4 * 4));
        }
        __syncthreads();

        // 8 partial dot products (one per batch), K-slice of 64, packed FMAs.
        float accs[8];
#pragma unroll
        for (int b = 0; b < 8; ++b) {
            const ulonglong2* hp = (const ulonglong2*)(hs + b * NH + k0);
            ull a0 = 0ull, a1 = 0ull;
#pragma unroll
            for (int c = 0; c < 16; ++c) {
                ulonglong2 hv = hp[c];   // broadcast LDS.128 (all lanes same addr)
                FFMA2(a0, w2[2 * c],     hv.x, a0);
                FFMA2(a1, w2[2 * c + 1], hv.y, a1);
            }
            float2 f0 = unpack2(a0);
            float2 f1 = unpack2(a1);
            accs[b] = (f0.x + f0.y) + (f1.x + f1.y);
        }

        // Cross-warp reduction: part[warp][b][lane], conflict-free both ways.
#pragma unroll
        for (int b = 0; b < 8; ++b)
            part[warp * 256 + b * 32 + lane] = accs[b];
        __syncthreads();

        float s = 0.f;
#pragma unroll
        for (int w = 0; w < 8; ++w)
            s += part[w * 256 + warp * 32 + lane];

        const float hv = tanhf(s + pre);
        const int   bo = b0 + warp;
        hseq[((size_t)t * NB + bo) * NH + j] = hv;
        if (t == T_SEQ - 1 && hlast) hlast[(size_t)bo * NH + j] = hv;

        // Release stores, then grid barrier (monotonic counter).
        __threadfence();
        __syncthreads();
        if (threadIdx.x == 0) {
            atomicAdd(&g_bar, 1u);
            const unsigned target = (unsigned)(t + 1) * RG;
            while (*(volatile unsigned*)&g_bar < target) { }
            __threadfence();   // acquire
        }
        __syncthreads();

        hprev = hseq + (size_t)t * NB * NH;
    }
}

// ---------------------------------------------------------------------------
extern "C" void kernel_launch(void* const* d_in, const int* in_sizes, int n_in,
                              void* d_out, int out_size)
{
    const float* x   = (const float*)d_in[0];
    const float* h0  = (const float*)d_in[1];
    const float* Wih = (const float*)d_in[2];
    const float* Whh = (const float*)d_in[3];
    const float* bih = (const float*)d_in[4];
    const float* bhh = (const float*)d_in[5];
    float* out = (float*)d_out;

    float* hlast = nullptr;
    if (out_size >= (int)((size_t)T_SEQ * NB * NH + NB * NH))
        hlast = out + (size_t)T_SEQ * NB * NH;

    reset_bar<<<1, 1>>>();

    dim3 grid(NH / BN, (T_SEQ * NB) / BM);   // (8, 256)
    gemm_xw<<<grid, 256>>>(x, Wih, bih, bhh);

    rnn_recur<<<RG, RT>>>(h0, Whh, out, hlast);
}